// round 5
// baseline (speedup 1.0000x reference)
#include <cuda_runtime.h>
#include <math.h>

#define MAXB 4096
// Per-block partials, transposed: g_part[component*MAXB + block].
// Fully overwritten each run -> no zeroing needed.
__device__ float    g_part[30 * MAXB];
__device__ unsigned g_count = 0;   // auto-resets via atomicInc wrap

// Order-preserving float -> uint mapping (total order incl. -INF).
__device__ __forceinline__ unsigned f2ord(float f) {
    unsigned b = __float_as_uint(f);
    return (b & 0x80000000u) ? ~b : (b | 0x80000000u);
}
__device__ __forceinline__ float ord2f(unsigned u) {
    return __uint_as_float((u & 0x80000000u) ? (u ^ 0x80000000u) : ~u);
}

// Warp argmax via redux: max value, min index on ties (first occurrence).
__device__ __forceinline__ void warp_argmax(float v, int idx, float& vout, int& iout) {
    unsigned u  = f2ord(v);
    unsigned um = __reduce_max_sync(0xffffffffu, u);
    unsigned cand = (u == um) ? (unsigned)idx : 0x7fffffffu;
    iout = (int)__reduce_min_sync(0xffffffffu, cand);
    vout = ord2f(um);
}

__device__ __forceinline__ void lane_max4(float4 x, int b, float& v, int& idx) {
    if (x.x > v) { v = x.x; idx = b;     }
    if (x.y > v) { v = x.y; idx = b + 1; }
    if (x.z > v) { v = x.z; idx = b + 2; }
    if (x.w > v) { v = x.w; idx = b + 3; }
}

__device__ __forceinline__ void accum_bin(float* slice, float v, int idx,
                                          const void* labels, int row, int lab64) {
    float conf = __expf(v);
    int bin = (int)ceilf(conf * 10.0f) - 1;
    if (bin >= 0 && bin < 10) {
        int lab;
        if (lab64) lab = (int)((const long long*)labels)[row];
        else       lab = ((const int*)labels)[row];
        slice[bin * 3 + 0] += 1.0f;
        slice[bin * 3 + 1] += conf;
        slice[bin * 3 + 2] += (idx == lab) ? 1.0f : 0.0f;
    }
}

// Single fused kernel: warp processes 8 rows/iter; per-block partials;
// last-done block reduces partials and writes the scalar ECE.
__global__ __launch_bounds__(256) void ece_fused_kernel(
    const float* __restrict__ logits,
    const void*  __restrict__ labels,
    float* __restrict__ out,
    int N, int C)
{
    __shared__ float sb[8][30];
    __shared__ int   s_lab64;
    __shared__ bool  s_last;
    __shared__ double sbins[30];

    const int warp = threadIdx.x >> 5;
    const int lane = threadIdx.x & 31;

    // Inline label-dtype probe (warp 0): interpret first P entries as int64;
    // any value outside [0,C) proves int32 (random int32 label pairs form
    // values >= 2^32 with overwhelming probability). Deterministic.
    if (warp == 0) {
        const long long* p = (const long long*)labels;
        int P = N / 2; if (P > 256) P = 256;
        bool bad = false;
        for (int i = lane; i < P; i += 32) {
            long long v = p[i];
            if (v < 0 || v >= (long long)C) bad = true;
        }
        unsigned any_bad = __ballot_sync(0xffffffffu, bad);
        if (lane == 0) s_lab64 = any_bad ? 0 : 1;
    }
    if (lane < 30) sb[warp][lane] = 0.0f;
    __syncthreads();

    float* slice = sb[warp];
    const int lab64 = s_lab64;
    const int warpsTotal = gridDim.x * 8;
    const int gwarp = blockIdx.x * 8 + warp;
    const int C4 = C >> 2;

    if ((C & 3) == 0 && C4 <= 32) {
        const bool act = (lane < C4);
        const int b = lane << 2;
        const int nChunks = N >> 3;   // groups of 8 rows
        const float4 NEG = make_float4(-INFINITY, -INFINITY, -INFINITY, -INFINITY);

        for (int ch = gwarp; ch < nChunks; ch += warpsTotal) {
            const int r0 = ch << 3;
            const float4* p = reinterpret_cast<const float4*>(logits + (size_t)r0 * C) + lane;

            // Issue all 8 streaming loads before any reduce (MLP=8/warp).
            float4 x[8];
            #pragma unroll
            for (int r = 0; r < 8; r++)
                x[r] = act ? __ldcs(p + r * C4) : NEG;

            float v[8]; int ix[8];
            #pragma unroll
            for (int r = 0; r < 8; r++) {
                float lv = -INFINITY; int li = 0x7fffffff;
                lane_max4(x[r], b, lv, li);
                warp_argmax(lv, li, v[r], ix[r]);
            }

            if (lane == 0) {
                #pragma unroll
                for (int r = 0; r < 8; r++)
                    accum_bin(slice, v[r], ix[r], labels, r0 + r, lab64);
            }
        }

        // Tail rows (N % 8).
        for (int row = (nChunks << 3) + gwarp; row < N; row += warpsTotal) {
            const float4* p = reinterpret_cast<const float4*>(logits + (size_t)row * C);
            float lv = -INFINITY; int li = 0x7fffffff;
            if (act) { float4 xx = __ldcs(p + lane); lane_max4(xx, b, lv, li); }
            float vv; int ii;
            warp_argmax(lv, li, vv, ii);
            if (lane == 0) accum_bin(slice, vv, ii, labels, row, lab64);
        }
    } else {
        // Generic fallback.
        for (int row = gwarp; row < N; row += warpsTotal) {
            float lv = -INFINITY; int li = 0x7fffffff;
            const float* p = logits + (size_t)row * C;
            for (int c = lane; c < C; c += 32) {
                float xx = p[c];
                if (xx > lv) { lv = xx; li = c; }
            }
            float vv; int ii;
            warp_argmax(lv, li, vv, ii);
            if (lane == 0) accum_bin(slice, vv, ii, labels, row, lab64);
        }
    }

    __syncthreads();

    // Block reduce 8 warp slices -> transposed per-block partials (coalesced
    // for the final reducer).
    int t = threadIdx.x;
    if (t < 30) {
        float s = 0.0f;
        #pragma unroll
        for (int w = 0; w < 8; w++) s += sb[w][t];
        g_part[t * MAXB + blockIdx.x] = s;
    }

    // Last-block-done: atomicInc wraps to 0 at gridDim.x-1 -> auto-reset per
    // launch, deterministic across graph replays.
    if (t == 0) {
        __threadfence();
        unsigned old = atomicInc(&g_count, gridDim.x - 1);
        s_last = (old == gridDim.x - 1);
    }
    __syncthreads();

    if (s_last) {
        const int nb = gridDim.x;
        // 8 warps cover 30 components; coalesced float loads, double accum.
        for (int c = warp; c < 30; c += 8) {
            double s = 0.0;
            const float* pc = &g_part[c * MAXB];
            for (int i = lane; i < nb; i += 32) s += (double)pc[i];
            #pragma unroll
            for (int off = 16; off; off >>= 1)
                s += __shfl_down_sync(0xffffffffu, s, off);
            if (lane == 0) sbins[c] = s;
        }
        __syncthreads();

        if (t == 0) {
            double ece = 0.0, n = (double)N;
            #pragma unroll
            for (int b = 0; b < 10; b++) {
                double cnt = sbins[b * 3 + 0];
                double sc  = sbins[b * 3 + 1];
                double sa  = sbins[b * 3 + 2];
                if (cnt > 0.0) ece += fabs(sc / cnt - sa / cnt) * (cnt / n);
            }
            out[0] = (float)ece;
        }
    }
}

extern "C" void kernel_launch(void* const* d_in, const int* in_sizes, int n_in,
                              void* d_out, int out_size)
{
    // Logits is the (much) larger buffer.
    int li = 0, bi = 1;
    if (in_sizes[1] > in_sizes[0]) { li = 1; bi = 0; }

    const float* logits = (const float*)d_in[li];
    const void*  labels = d_in[bi];

    int N = in_sizes[bi];
    int C = in_sizes[li] / N;

    int blocks = 1216;                               // 8 blocks/SM target
    long long maxBlocks = ((long long)N + 63) / 64;  // 8 warps x 8 rows
    if (blocks > maxBlocks) blocks = (int)maxBlocks;
    if (blocks < 1) blocks = 1;
    if (blocks > MAXB) blocks = MAXB;

    ece_fused_kernel<<<blocks, 256>>>(logits, labels, (float*)d_out, N, C);
}

// round 6
// speedup vs baseline: 1.0512x; 1.0512x over previous
#include <cuda_runtime.h>
#include <math.h>

#define MAXB 4096
// Per-block partials, transposed: g_part[component*MAXB + block].
// Fully overwritten each run -> no zeroing needed.
__device__ float    g_part[30 * MAXB];
__device__ unsigned g_count = 0;   // auto-resets via atomicInc wrap

// Branch-free order-preserving float -> uint mapping.
__device__ __forceinline__ unsigned f2ord(float f) {
    unsigned b = __float_as_uint(f);
    return b ^ ((unsigned)((int)b >> 31) | 0x80000000u);
}
__device__ __forceinline__ float ord2f(unsigned u) {
    return __uint_as_float(u ^ ((unsigned)((int)(~u) >> 31) | 0x80000000u));
}

__device__ __forceinline__ void accum_bin(float* slice, float v, int idx,
                                          const void* labels, int row, int lab64) {
    float conf = __expf(v);
    int bin = (int)ceilf(conf * 10.0f) - 1;
    if (bin >= 0 && bin < 10) {
        int lab;
        if (lab64) lab = (int)((const long long*)labels)[row];
        else       lab = ((const int*)labels)[row];
        slice[bin * 3 + 0] += 1.0f;
        slice[bin * 3 + 1] += conf;
        slice[bin * 3 + 2] += (idx == lab) ? 1.0f : 0.0f;
    }
}

// Fast row reduce: FMAX tree for value, equality scan for first-occurrence
// index, REDUX max/min across the warp.
__device__ __forceinline__ void row_argmax(float4 x, int b, float& vmax, int& imin) {
    float lv = fmaxf(fmaxf(x.x, x.y), fmaxf(x.z, x.w));
    unsigned u  = f2ord(lv);
    unsigned um = __reduce_max_sync(0xffffffffu, u);
    int li = b + ((x.x == lv) ? 0 : (x.y == lv) ? 1 : (x.z == lv) ? 2 : 3);
    unsigned cand = (u == um) ? (unsigned)li : 0xffffffffu;
    imin = (int)__reduce_min_sync(0xffffffffu, cand);
    vmax = ord2f(um);
}

// Single fused kernel: warp processes 8 rows/iter; per-block partials;
// last-done block reduces partials and writes the scalar ECE.
__global__ __launch_bounds__(256) void ece_fused_kernel(
    const float* __restrict__ logits,
    const void*  __restrict__ labels,
    float* __restrict__ out,
    int N, int C)
{
    __shared__ float sb[8][30];
    __shared__ int   s_lab64;
    __shared__ bool  s_last;
    __shared__ double sbins[30];

    const int warp = threadIdx.x >> 5;
    const int lane = threadIdx.x & 31;

    // Inline label-dtype probe (warp 0): interpret first P entries as int64;
    // any value outside [0,C) proves int32 (random int32 label pairs form
    // values >= 2^32 with overwhelming probability). Deterministic.
    if (warp == 0) {
        const long long* p = (const long long*)labels;
        int P = N / 2; if (P > 256) P = 256;
        bool bad = false;
        for (int i = lane; i < P; i += 32) {
            long long v = p[i];
            if (v < 0 || v >= (long long)C) bad = true;
        }
        unsigned any_bad = __ballot_sync(0xffffffffu, bad);
        if (lane == 0) s_lab64 = any_bad ? 0 : 1;
    }
    if (lane < 30) sb[warp][lane] = 0.0f;
    __syncthreads();

    float* slice = sb[warp];
    const int lab64 = s_lab64;
    const int warpsTotal = gridDim.x * 8;
    const int gwarp = blockIdx.x * 8 + warp;
    const int C4 = C >> 2;

    if ((C & 3) == 0 && C4 >= 1 && C4 <= 32) {
        // Inactive lanes (lane >= C4) re-load the row's first float4.
        // Duplicates can never strictly exceed the genuine max, and on
        // equality the min-index tie-break (their b >= C) always selects
        // the genuine occurrence. Branch-free inner loop.
        const int off = (lane < C4) ? lane : 0;
        const int b   = lane << 2;
        const int nChunks = N >> 3;   // groups of 8 rows

        for (int ch = gwarp; ch < nChunks; ch += warpsTotal) {
            const int r0 = ch << 3;
            const float4* p = reinterpret_cast<const float4*>(logits + (size_t)r0 * C) + off;

            // Issue all 8 streaming loads before any reduce (MLP=8/warp).
            float4 x[8];
            #pragma unroll
            for (int r = 0; r < 8; r++)
                x[r] = __ldcs(p + r * C4);

            float v[8]; int ix[8];
            #pragma unroll
            for (int r = 0; r < 8; r++)
                row_argmax(x[r], b, v[r], ix[r]);

            if (lane == 0) {
                #pragma unroll
                for (int r = 0; r < 8; r++)
                    accum_bin(slice, v[r], ix[r], labels, r0 + r, lab64);
            }
        }

        // Tail rows (N % 8).
        for (int row = (nChunks << 3) + gwarp; row < N; row += warpsTotal) {
            const float4* p = reinterpret_cast<const float4*>(logits + (size_t)row * C);
            float4 xx = __ldcs(p + off);
            float vv; int ii;
            row_argmax(xx, b, vv, ii);
            if (lane == 0) accum_bin(slice, vv, ii, labels, row, lab64);
        }
    } else {
        // Generic fallback.
        for (int row = gwarp; row < N; row += warpsTotal) {
            float lv = -INFINITY; int li = 0x7fffffff;
            const float* p = logits + (size_t)row * C;
            for (int c = lane; c < C; c += 32) {
                float xx = p[c];
                if (xx > lv) { lv = xx; li = c; }
            }
            unsigned u  = f2ord(lv);
            unsigned um = __reduce_max_sync(0xffffffffu, u);
            unsigned cand = (u == um) ? (unsigned)li : 0xffffffffu;
            int ii = (int)__reduce_min_sync(0xffffffffu, cand);
            if (lane == 0) accum_bin(slice, ord2f(um), ii, labels, row, lab64);
        }
    }

    __syncthreads();

    // Block reduce 8 warp slices -> transposed per-block partials.
    int t = threadIdx.x;
    if (t < 30) {
        float s = 0.0f;
        #pragma unroll
        for (int w = 0; w < 8; w++) s += sb[w][t];
        g_part[t * MAXB + blockIdx.x] = s;
    }

    // Last-block-done: atomicInc wraps to 0 at gridDim.x-1 -> auto-reset per
    // launch, deterministic across graph replays.
    if (t == 0) {
        __threadfence();
        unsigned old = atomicInc(&g_count, gridDim.x - 1);
        s_last = (old == gridDim.x - 1);
    }
    __syncthreads();

    if (s_last) {
        const int nb = gridDim.x;
        // 8 warps cover 30 components; coalesced float loads, double accum.
        for (int c = warp; c < 30; c += 8) {
            double s = 0.0;
            const float* pc = &g_part[c * MAXB];
            for (int i = lane; i < nb; i += 32) s += (double)pc[i];
            #pragma unroll
            for (int offr = 16; offr; offr >>= 1)
                s += __shfl_down_sync(0xffffffffu, s, offr);
            if (lane == 0) sbins[c] = s;
        }
        __syncthreads();

        if (t == 0) {
            double ece = 0.0, n = (double)N;
            #pragma unroll
            for (int bb = 0; bb < 10; bb++) {
                double cnt = sbins[bb * 3 + 0];
                double sc  = sbins[bb * 3 + 1];
                double sa  = sbins[bb * 3 + 2];
                if (cnt > 0.0) ece += fabs(sc / cnt - sa / cnt) * (cnt / n);
            }
            out[0] = (float)ece;
        }
    }
}

extern "C" void kernel_launch(void* const* d_in, const int* in_sizes, int n_in,
                              void* d_out, int out_size)
{
    // Logits is the (much) larger buffer.
    int li = 0, bi = 1;
    if (in_sizes[1] > in_sizes[0]) { li = 1; bi = 0; }

    const float* logits = (const float*)d_in[li];
    const void*  labels = d_in[bi];

    int N = in_sizes[bi];
    int C = in_sizes[li] / N;

    int blocks = 1216;                               // ~4 resident blocks/SM, 2 waves
    long long maxBlocks = ((long long)N + 63) / 64;  // 8 warps x 8 rows
    if (blocks > maxBlocks) blocks = (int)maxBlocks;
    if (blocks < 1) blocks = 1;
    if (blocks > MAXB) blocks = MAXB;

    ece_fused_kernel<<<blocks, 256>>>(logits, labels, (float*)d_out, N, C);
}

// round 7
// speedup vs baseline: 1.1091x; 1.0551x over previous
#include <cuda_runtime.h>
#include <math.h>

#define MAXB 4096
#define NROW 8   // rows per warp-chunk; lanes 0..NROW-1 own one row each
// Per-block partials, transposed: g_part[component*MAXB + block].
// Fully overwritten each run -> no zeroing needed.
__device__ float    g_part[30 * MAXB];
__device__ unsigned g_count = 0;   // auto-resets via atomicInc wrap

// Branch-free order-preserving float -> uint mapping.
__device__ __forceinline__ unsigned f2ord(float f) {
    unsigned b = __float_as_uint(f);
    return b ^ ((unsigned)((int)b >> 31) | 0x80000000u);
}
__device__ __forceinline__ float ord2f(unsigned u) {
    return __uint_as_float(u ^ ((unsigned)((int)(~u) >> 31) | 0x80000000u));
}

// Fast row reduce: FMAX tree for value, equality scan for first-occurrence
// index, REDUX max/min across the warp. Results broadcast to all lanes.
__device__ __forceinline__ void row_argmax(float4 x, int b, float& vmax, int& imin) {
    float lv = fmaxf(fmaxf(x.x, x.y), fmaxf(x.z, x.w));
    unsigned u  = f2ord(lv);
    unsigned um = __reduce_max_sync(0xffffffffu, u);
    int li = b + ((x.x == lv) ? 0 : (x.y == lv) ? 1 : (x.z == lv) ? 2 : 3);
    unsigned cand = (u == um) ? (unsigned)li : 0xffffffffu;
    imin = (int)__reduce_min_sync(0xffffffffu, cand);
    vmax = ord2f(um);
}

// Single fused kernel: warp processes NROW rows/iter; lanes 0..NROW-1 own one
// row's epilogue each with private smem slices (no atomics); per-block
// partials; last-done block reduces partials and writes the scalar ECE.
__global__ __launch_bounds__(256) void ece_fused_kernel(
    const float* __restrict__ logits,
    const void*  __restrict__ labels,
    float* __restrict__ out,
    int N, int C)
{
    __shared__ float sb[8][NROW][30];   // [warp][owner lane][component]
    __shared__ int   s_lab64;
    __shared__ bool  s_last;
    __shared__ double sbins[30];

    const int warp = threadIdx.x >> 5;
    const int lane = threadIdx.x & 31;

    // Inline label-dtype probe (warp 0): interpret first P entries as int64;
    // any value outside [0,C) proves int32 (random int32 label pairs form
    // values >= 2^32 with overwhelming probability). Deterministic.
    if (warp == 0) {
        const long long* p = (const long long*)labels;
        int P = N / 2; if (P > 256) P = 256;
        bool bad = false;
        for (int i = lane; i < P; i += 32) {
            long long v = p[i];
            if (v < 0 || v >= (long long)C) bad = true;
        }
        unsigned any_bad = __ballot_sync(0xffffffffu, bad);
        if (lane == 0) s_lab64 = any_bad ? 0 : 1;
    }
    {
        float* z = &sb[0][0][0];
        for (int i = threadIdx.x; i < 8 * NROW * 30; i += 256) z[i] = 0.0f;
    }
    __syncthreads();

    const int lab64 = s_lab64;
    const int warpsTotal = gridDim.x * 8;
    const int gwarp = blockIdx.x * 8 + warp;
    const int C4 = C >> 2;

    if ((C & 3) == 0 && C4 >= 1 && C4 <= 32) {
        // Inactive lanes (lane >= C4) re-load the row's first float4.
        // Duplicates can never strictly exceed the genuine max, and on
        // equality the min-index tie-break (their b >= C) always selects
        // the genuine occurrence. Branch-free inner loop.
        const int off = (lane < C4) ? lane : 0;
        const int b   = lane << 2;
        const int nChunks = N / NROW;
        float* myslice = sb[warp][lane & (NROW - 1)];

        for (int ch = gwarp; ch < nChunks; ch += warpsTotal) {
            const int r0 = ch * NROW;
            const float4* p = reinterpret_cast<const float4*>(logits + (size_t)r0 * C) + off;

            // Issue all NROW streaming loads before any reduce.
            float4 x[NROW];
            #pragma unroll
            for (int r = 0; r < NROW; r++)
                x[r] = __ldcs(p + r * C4);

            // Reduce each row; lane r keeps row r's result (REDUX broadcasts).
            float vk = 0.0f; int ik = -1;
            #pragma unroll
            for (int r = 0; r < NROW; r++) {
                float vmax; int imin;
                row_argmax(x[r], b, vmax, imin);
                if (lane == r) { vk = vmax; ik = imin; }
            }

            // Parallel epilogue: lanes 0..NROW-1 each handle their row.
            if (lane < NROW) {
                int row = r0 + lane;
                float conf = __expf(vk);
                int bin = (int)ceilf(conf * 10.0f) - 1;
                if (bin >= 0 && bin < 10) {
                    int lab;
                    if (lab64) lab = (int)((const long long*)labels)[row];
                    else       lab = ((const int*)labels)[row];
                    myslice[bin * 3 + 0] += 1.0f;
                    myslice[bin * 3 + 1] += conf;
                    myslice[bin * 3 + 2] += (ik == lab) ? 1.0f : 0.0f;
                }
            }
        }

        // Tail rows (N % NROW).
        for (int row = nChunks * NROW + gwarp; row < N; row += warpsTotal) {
            const float4* p = reinterpret_cast<const float4*>(logits + (size_t)row * C);
            float4 xx = __ldcs(p + off);
            float vv; int ii;
            row_argmax(xx, b, vv, ii);
            if (lane == 0) {
                float conf = __expf(vv);
                int bin = (int)ceilf(conf * 10.0f) - 1;
                if (bin >= 0 && bin < 10) {
                    int lab;
                    if (lab64) lab = (int)((const long long*)labels)[row];
                    else       lab = ((const int*)labels)[row];
                    sb[warp][0][bin * 3 + 0] += 1.0f;
                    sb[warp][0][bin * 3 + 1] += conf;
                    sb[warp][0][bin * 3 + 2] += (ii == lab) ? 1.0f : 0.0f;
                }
            }
        }
    } else {
        // Generic fallback: warp per row.
        for (int row = gwarp; row < N; row += warpsTotal) {
            float lv = -INFINITY; int li = 0x7fffffff;
            const float* p = logits + (size_t)row * C;
            for (int c = lane; c < C; c += 32) {
                float xx = p[c];
                if (xx > lv) { lv = xx; li = c; }
            }
            unsigned u  = f2ord(lv);
            unsigned um = __reduce_max_sync(0xffffffffu, u);
            unsigned cand = (u == um) ? (unsigned)li : 0xffffffffu;
            int ii = (int)__reduce_min_sync(0xffffffffu, cand);
            if (lane == 0) {
                float vv = ord2f(um);
                float conf = __expf(vv);
                int bin = (int)ceilf(conf * 10.0f) - 1;
                if (bin >= 0 && bin < 10) {
                    int lab;
                    if (lab64) lab = (int)((const long long*)labels)[row];
                    else       lab = ((const int*)labels)[row];
                    sb[warp][0][bin * 3 + 0] += 1.0f;
                    sb[warp][0][bin * 3 + 1] += conf;
                    sb[warp][0][bin * 3 + 2] += (ii == lab) ? 1.0f : 0.0f;
                }
            }
        }
    }

    __syncthreads();

    // Block reduce 8*NROW slices -> transposed per-block partials.
    int t = threadIdx.x;
    if (t < 30) {
        float s = 0.0f;
        #pragma unroll
        for (int w = 0; w < 8; w++)
            #pragma unroll
            for (int r = 0; r < NROW; r++)
                s += sb[w][r][t];
        g_part[t * MAXB + blockIdx.x] = s;
    }

    // Last-block-done: atomicInc wraps to 0 at gridDim.x-1 -> auto-reset per
    // launch, deterministic across graph replays.
    if (t == 0) {
        __threadfence();
        unsigned old = atomicInc(&g_count, gridDim.x - 1);
        s_last = (old == gridDim.x - 1);
    }
    __syncthreads();

    if (s_last) {
        const int nb = gridDim.x;
        // 8 warps cover 30 components; coalesced float loads, double accum.
        for (int c = warp; c < 30; c += 8) {
            double s = 0.0;
            const float* pc = &g_part[c * MAXB];
            for (int i = lane; i < nb; i += 32) s += (double)pc[i];
            #pragma unroll
            for (int offr = 16; offr; offr >>= 1)
                s += __shfl_down_sync(0xffffffffu, s, offr);
            if (lane == 0) sbins[c] = s;
        }
        __syncthreads();

        if (t == 0) {
            double ece = 0.0, n = (double)N;
            #pragma unroll
            for (int bb = 0; bb < 10; bb++) {
                double cnt = sbins[bb * 3 + 0];
                double sc  = sbins[bb * 3 + 1];
                double sa  = sbins[bb * 3 + 2];
                if (cnt > 0.0) ece += fabs(sc / cnt - sa / cnt) * (cnt / n);
            }
            out[0] = (float)ece;
        }
    }
}

extern "C" void kernel_launch(void* const* d_in, const int* in_sizes, int n_in,
                              void* d_out, int out_size)
{
    // Logits is the (much) larger buffer.
    int li = 0, bi = 1;
    if (in_sizes[1] > in_sizes[0]) { li = 1; bi = 0; }

    const float* logits = (const float*)d_in[li];
    const void*  labels = d_in[bi];

    int N = in_sizes[bi];
    int C = in_sizes[li] / N;

    int blocks = 1216;
    long long maxBlocks = ((long long)N + 8LL * NROW - 1) / (8LL * NROW);
    if (blocks > maxBlocks) blocks = (int)maxBlocks;
    if (blocks < 1) blocks = 1;
    if (blocks > MAXB) blocks = MAXB;

    ece_fused_kernel<<<blocks, 256>>>(logits, labels, (float*)d_out, N, C);
}